// round 3
// baseline (speedup 1.0000x reference)
#include <cuda_runtime.h>
#include <cstdint>

#define IMAGE_H 200
#define IMAGE_W 200
#define IMG_ELEMS (IMAGE_H * IMAGE_W * 3)    // 120000 floats per image
#define N_STEPS 400                           // IMAGE_H + IMAGE_W, safe cap

__global__ void __launch_bounds__(256) draw_rope_kernel(
    const float* __restrict__ x,          // [M, 6] = (x0,y0,x1,y1,x2,y2)
    const float* __restrict__ resolution, // [2]
    const float* __restrict__ origin,     // [2]
    float* __restrict__ out)              // [M, 200, 200, 3] float32
{
    const int m = blockIdx.x;
    float* img = out + (size_t)m * IMG_ELEMS;

    // ---- Phase 1: zero-fill this image (coalesced 16B stores) ----
    {
        float4 z = make_float4(0.f, 0.f, 0.f, 0.f);
        float4* p = reinterpret_cast<float4*>(img);
        const int n4 = IMG_ELEMS / 4; // 30000
        for (int i = threadIdx.x; i < n4; i += blockDim.x) p[i] = z;
    }

    // ---- Compute the 3 rope points' pixel indices ----
    // row = floor(y / resolution[0] + origin[0]); col = floor(x / resolution[1] + origin[1])
    const float res0 = resolution[0];
    const float res1 = resolution[1];
    const float org0 = origin[0];
    const float org1 = origin[1];
    const float* px = x + (size_t)m * 6;

    int rows[3], cols[3];
#pragma unroll
    for (int i = 0; i < 3; i++) {
        float xf = px[2 * i + 0];
        float yf = px[2 * i + 1];
        rows[i] = (int)floorf(yf / res0 + org0);
        cols[i] = (int)floorf(xf / res1 + org1);
    }

    __syncthreads(); // fill complete before any line pixel is written

    // ---- Phase 2: two Bresenham segments, one per thread (exact reference replica) ----
    if (threadIdx.x < 2) {
        const int s = threadIdx.x;           // segment index: p[s] -> p[s+1]
        int c = cols[s],     r = rows[s];
        const int c1 = cols[s + 1], r1 = rows[s + 1];
        const int dx = abs(c1 - c);
        const int dy = -abs(r1 - r);
        const int sc = (c < c1) ? 1 : -1;
        const int sr = (r < r1) ? 1 : -1;
        int err = dx + dy;

        // Reference scan body: emit current point (valid while !done), then
        // done |= at-endpoint, then conditional double-step. Serial equivalent:
        for (int it = 0; it < N_STEPS; ++it) {
            if ((unsigned)r < (unsigned)IMAGE_H && (unsigned)c < (unsigned)IMAGE_W) {
                float* q = img + (r * IMAGE_W + c) * 3;
                q[0] = 128.f; q[1] = 128.f; q[2] = 128.f;
            }
            if (c == c1 && r == r1) break;
            int e2 = 2 * err;
            if (e2 >= dy) { err += dy; c += sc; }
            if (e2 <= dx) { err += dx; r += sr; }
        }
    }

    __syncthreads(); // all line pixels visible before endpoint overwrites

    // ---- Phase 3: endpoint markers, reference order: red, red, green ----
    if (threadIdx.x == 0) {
        const float R[3][3] = { {255.f, 0.f, 0.f}, {255.f, 0.f, 0.f}, {0.f, 255.f, 0.f} };
#pragma unroll
        for (int i = 0; i < 3; i++) {
            int r = rows[i], cidx = cols[i];
            if ((unsigned)r < (unsigned)IMAGE_H && (unsigned)cidx < (unsigned)IMAGE_W) {
                float* q = img + (r * IMAGE_W + cidx) * 3;
                q[0] = R[i][0]; q[1] = R[i][1]; q[2] = R[i][2];
            }
        }
    }
}

extern "C" void kernel_launch(void* const* d_in, const int* in_sizes, int n_in,
                              void* d_out, int out_size) {
    const float* x          = (const float*)d_in[0]; // [B*T*6] float32
    const float* resolution = (const float*)d_in[1]; // [2]
    const float* origin     = (const float*)d_in[2]; // [2]
    float* out              = (float*)d_out;         // [B,T,200,200,3] float32

    const int M = in_sizes[0] / 6; // B*T = 800 images
    draw_rope_kernel<<<M, 256>>>(x, resolution, origin, out);
}

// round 4
// speedup vs baseline: 1.0920x; 1.0920x over previous
#include <cuda_runtime.h>
#include <cstdint>

#define IMAGE_H 200
#define IMAGE_W 200
#define IMG_ELEMS (IMAGE_H * IMAGE_W * 3)    // 120000 floats per image
#define N_STEPS 400                           // IMAGE_H + IMAGE_W, safe cap

// ---------------- Kernel 1: grid-wide zero fill (128-bit stores) ----------------
__global__ void __launch_bounds__(256) fill_zero_kernel(float4* __restrict__ p, int n4)
{
    const float4 z = make_float4(0.f, 0.f, 0.f, 0.f);
    int i = blockIdx.x * blockDim.x + threadIdx.x;
    const int stride = gridDim.x * blockDim.x;
#pragma unroll 4
    for (; i < n4; i += stride) p[i] = z;
}

// ---------------- Kernel 2: draw lines + endpoint markers ----------------
__global__ void __launch_bounds__(64) draw_rope_kernel(
    const float* __restrict__ x,          // [M, 6] = (x0,y0,x1,y1,x2,y2)
    const float* __restrict__ resolution, // [2]
    const float* __restrict__ origin,     // [2]
    float* __restrict__ out)              // [M, 200, 200, 3] float32
{
    const int m = blockIdx.x;
    float* img = out + (size_t)m * IMG_ELEMS;

    // row = floor(y / resolution[0] + origin[0]); col = floor(x / resolution[1] + origin[1])
    const float res0 = resolution[0];
    const float res1 = resolution[1];
    const float org0 = origin[0];
    const float org1 = origin[1];
    const float* px = x + (size_t)m * 6;

    int rows[3], cols[3];
#pragma unroll
    for (int i = 0; i < 3; i++) {
        float xf = px[2 * i + 0];
        float yf = px[2 * i + 1];
        rows[i] = (int)floorf(yf / res0 + org0);
        cols[i] = (int)floorf(xf / res1 + org1);
    }

    // ---- two Bresenham segments, one per thread (exact reference replica) ----
    if (threadIdx.x < 2) {
        const int s = threadIdx.x;           // segment index: p[s] -> p[s+1]
        int c = cols[s],     r = rows[s];
        const int c1 = cols[s + 1], r1 = rows[s + 1];
        const int dx = abs(c1 - c);
        const int dy = -abs(r1 - r);
        const int sc = (c < c1) ? 1 : -1;
        const int sr = (r < r1) ? 1 : -1;
        int err = dx + dy;

        // Reference scan body: emit current point (valid while !done), then
        // done |= at-endpoint, then conditional double-step. Serial equivalent:
        for (int it = 0; it < N_STEPS; ++it) {
            if ((unsigned)r < (unsigned)IMAGE_H && (unsigned)c < (unsigned)IMAGE_W) {
                float* q = img + (r * IMAGE_W + c) * 3;
                q[0] = 128.f; q[1] = 128.f; q[2] = 128.f;
            }
            if (c == c1 && r == r1) break;
            int e2 = 2 * err;
            if (e2 >= dy) { err += dy; c += sc; }
            if (e2 <= dx) { err += dx; r += sr; }
        }
    }

    __syncthreads(); // all line pixels visible before endpoint overwrites

    // ---- endpoint markers, reference order: red, red, green ----
    if (threadIdx.x == 0) {
        const float R[3][3] = { {255.f, 0.f, 0.f}, {255.f, 0.f, 0.f}, {0.f, 255.f, 0.f} };
#pragma unroll
        for (int i = 0; i < 3; i++) {
            int r = rows[i], cidx = cols[i];
            if ((unsigned)r < (unsigned)IMAGE_H && (unsigned)cidx < (unsigned)IMAGE_W) {
                float* q = img + (r * IMAGE_W + cidx) * 3;
                q[0] = R[i][0]; q[1] = R[i][1]; q[2] = R[i][2];
            }
        }
    }
}

extern "C" void kernel_launch(void* const* d_in, const int* in_sizes, int n_in,
                              void* d_out, int out_size) {
    const float* x          = (const float*)d_in[0]; // [B*T*6] float32
    const float* resolution = (const float*)d_in[1]; // [2]
    const float* origin     = (const float*)d_in[2]; // [2]
    float* out              = (float*)d_out;         // [B,T,200,200,3] float32

    const int M = in_sizes[0] / 6; // B*T = 800 images

    const int n4 = (M * IMG_ELEMS) / 4; // 24,000,000 float4s
    const int fill_blocks = 2368;       // 148 SMs * 16, ~40 iters/thread
    fill_zero_kernel<<<fill_blocks, 256>>>((float4*)out, n4);

    draw_rope_kernel<<<M, 64>>>(x, resolution, origin, out);
}

// round 5
// speedup vs baseline: 1.1890x; 1.0889x over previous
#include <cuda_runtime.h>
#include <cstdint>

#define IMAGE_H 200
#define IMAGE_W 200
#define IMG_ELEMS (IMAGE_H * IMAGE_W * 3)    // 120000 floats per image

// ---------------- Kernel 1: grid-wide zero fill (128-bit stores) ----------------
__global__ void __launch_bounds__(256) fill_zero_kernel(float4* __restrict__ p, int n4)
{
    const float4 z = make_float4(0.f, 0.f, 0.f, 0.f);
    int i = blockIdx.x * blockDim.x + threadIdx.x;
    const int stride = gridDim.x * blockDim.x;
#pragma unroll 4
    for (; i < n4; i += stride) p[i] = z;
}

// ---------------- Kernel 2: parallel closed-form Bresenham + markers ----------------
// Exact closed form of the reference's both-axis-step Bresenham:
//   major axis advances every iteration; minor steps after k iters:
//   m_k = floor((2*k*minor + major) / (2*major)); pixels k = 0..major inclusive.
__global__ void __launch_bounds__(128) draw_rope_kernel(
    const float* __restrict__ x,          // [M, 6] = (x0,y0,x1,y1,x2,y2)
    const float* __restrict__ resolution, // [2]
    const float* __restrict__ origin,     // [2]
    float* __restrict__ out)              // [M, 200, 200, 3] float32
{
    const int m = blockIdx.x;
    float* img = out + (size_t)m * IMG_ELEMS;

    // row = floor(y / resolution[0] + origin[0]); col = floor(x / resolution[1] + origin[1])
    const float res0 = resolution[0];
    const float res1 = resolution[1];
    const float org0 = origin[0];
    const float org1 = origin[1];
    const float* px = x + (size_t)m * 6;

    int rows[3], cols[3];
#pragma unroll
    for (int i = 0; i < 3; i++) {
        float xf = px[2 * i + 0];
        float yf = px[2 * i + 1];
        rows[i] = (int)floorf(yf / res0 + org0);
        cols[i] = (int)floorf(xf / res1 + org1);
    }

    // ---- two segments, pixels drawn fully in parallel across the block ----
#pragma unroll
    for (int s = 0; s < 2; s++) {
        const int c0 = cols[s],     r0 = rows[s];
        const int c1 = cols[s + 1], r1 = rows[s + 1];
        const int dx = abs(c1 - c0);
        const int D  = abs(r1 - r0);
        const int sc = (c0 < c1) ? 1 : -1;
        const int sr = (r0 < r1) ? 1 : -1;
        const bool xmajor = (dx >= D);
        const unsigned major = xmajor ? (unsigned)dx : (unsigned)D;
        const unsigned minor = xmajor ? (unsigned)D  : (unsigned)dx;

        if (major == 0u) {
            if (threadIdx.x == 0 &&
                (unsigned)r0 < (unsigned)IMAGE_H && (unsigned)c0 < (unsigned)IMAGE_W) {
                float* q = img + (r0 * IMAGE_W + c0) * 3;
                q[0] = 128.f; q[1] = 128.f; q[2] = 128.f;
            }
        } else {
            const unsigned den = 2u * major;
            for (unsigned k = threadIdx.x; k <= major; k += blockDim.x) {
                const int q_steps = (int)((2u * k * minor + major) / den);
                const int c = xmajor ? (c0 + (int)k * sc) : (c0 + q_steps * sc);
                const int r = xmajor ? (r0 + q_steps * sr) : (r0 + (int)k * sr);
                if ((unsigned)r < (unsigned)IMAGE_H && (unsigned)c < (unsigned)IMAGE_W) {
                    float* q = img + (r * IMAGE_W + c) * 3;
                    q[0] = 128.f; q[1] = 128.f; q[2] = 128.f;
                }
            }
        }
    }

    __syncthreads(); // all line pixels of this image visible before marker overwrites

    // ---- endpoint markers, reference order: red, red, green ----
    if (threadIdx.x == 0) {
        const float R[3][3] = { {255.f, 0.f, 0.f}, {255.f, 0.f, 0.f}, {0.f, 255.f, 0.f} };
#pragma unroll
        for (int i = 0; i < 3; i++) {
            int r = rows[i], cidx = cols[i];
            if ((unsigned)r < (unsigned)IMAGE_H && (unsigned)cidx < (unsigned)IMAGE_W) {
                float* q = img + (r * IMAGE_W + cidx) * 3;
                q[0] = R[i][0]; q[1] = R[i][1]; q[2] = R[i][2];
            }
        }
    }
}

extern "C" void kernel_launch(void* const* d_in, const int* in_sizes, int n_in,
                              void* d_out, int out_size) {
    const float* x          = (const float*)d_in[0]; // [B*T*6] float32
    const float* resolution = (const float*)d_in[1]; // [2]
    const float* origin     = (const float*)d_in[2]; // [2]
    float* out              = (float*)d_out;         // [B,T,200,200,3] float32

    const int M = in_sizes[0] / 6; // B*T = 800 images

    const int n4 = (M * IMG_ELEMS) / 4; // 24,000,000 float4s
    const int fill_blocks = 2368;       // 148 SMs * 16, ~40 iters/thread
    fill_zero_kernel<<<fill_blocks, 256>>>((float4*)out, n4);

    draw_rope_kernel<<<M, 128>>>(x, resolution, origin, out);
}

// round 6
// speedup vs baseline: 1.3031x; 1.0960x over previous
#include <cuda_runtime.h>
#include <cstdint>

#define IMAGE_H 200
#define IMAGE_W 200
#define IMG_BYTES (IMAGE_H * IMAGE_W * 3)    // 120000 smem bytes per image
#define IMG_ELEMS IMG_BYTES                   // float elems per output image
#define THREADS 512

// Fused: compose uint8 image in SMEM (zero + closed-form Bresenham + markers),
// then stream out as float32 — one clean 384MB store pass, no DRAM read-modify-write.
__global__ void __launch_bounds__(THREADS) draw_rope_fused(
    const float* __restrict__ x,          // [M, 6] = (x0,y0,x1,y1,x2,y2)
    const float* __restrict__ resolution, // [2]
    const float* __restrict__ origin,     // [2]
    float* __restrict__ out)              // [M, 200, 200, 3] float32
{
    extern __shared__ unsigned char s_img[]; // IMG_BYTES

    const int m = blockIdx.x;

    // ---- Phase 0: zero smem image ----
    {
        uint4 z = make_uint4(0u, 0u, 0u, 0u);
        uint4* s4 = reinterpret_cast<uint4*>(s_img);
        const int n16 = IMG_BYTES / 16; // 7500
        for (int i = threadIdx.x; i < n16; i += THREADS) s4[i] = z;
    }

    // ---- rope point pixel indices (all threads, registers) ----
    const float res0 = resolution[0];
    const float res1 = resolution[1];
    const float org0 = origin[0];
    const float org1 = origin[1];
    const float* px = x + (size_t)m * 6;

    int rows[3], cols[3];
#pragma unroll
    for (int i = 0; i < 3; i++) {
        float xf = px[2 * i + 0];
        float yf = px[2 * i + 1];
        rows[i] = (int)floorf(yf / res0 + org0);
        cols[i] = (int)floorf(xf / res1 + org1);
    }

    __syncthreads(); // zero-fill complete

    // ---- Phase 1: closed-form Bresenham into smem ----
    // m_k = floor((2*k*minor + major) / (2*major)), pixels k = 0..major inclusive
#pragma unroll
    for (int s = 0; s < 2; s++) {
        const int c0 = cols[s],     r0 = rows[s];
        const int c1 = cols[s + 1], r1 = rows[s + 1];
        const int dx = abs(c1 - c0);
        const int D  = abs(r1 - r0);
        const int sc = (c0 < c1) ? 1 : -1;
        const int sr = (r0 < r1) ? 1 : -1;
        const bool xmajor = (dx >= D);
        const unsigned major = xmajor ? (unsigned)dx : (unsigned)D;
        const unsigned minor = xmajor ? (unsigned)D  : (unsigned)dx;

        if (major == 0u) {
            if (threadIdx.x == 0 &&
                (unsigned)r0 < (unsigned)IMAGE_H && (unsigned)c0 < (unsigned)IMAGE_W) {
                unsigned char* q = s_img + (r0 * IMAGE_W + c0) * 3;
                q[0] = 128; q[1] = 128; q[2] = 128;
            }
        } else {
            const unsigned den = 2u * major;
            for (unsigned k = threadIdx.x; k <= major; k += THREADS) {
                const int qs = (int)((2u * k * minor + major) / den);
                const int c = xmajor ? (c0 + (int)k * sc) : (c0 + qs * sc);
                const int r = xmajor ? (r0 + qs * sr) : (r0 + (int)k * sr);
                if ((unsigned)r < (unsigned)IMAGE_H && (unsigned)c < (unsigned)IMAGE_W) {
                    unsigned char* q = s_img + (r * IMAGE_W + c) * 3;
                    q[0] = 128; q[1] = 128; q[2] = 128;
                }
            }
        }
    }

    __syncthreads(); // line pixels done before marker overwrites

    // ---- Phase 2: endpoint markers, reference order: red, red, green ----
    if (threadIdx.x == 0) {
        const unsigned char R[3][3] = { {255, 0, 0}, {255, 0, 0}, {0, 255, 0} };
#pragma unroll
        for (int i = 0; i < 3; i++) {
            int r = rows[i], cidx = cols[i];
            if ((unsigned)r < (unsigned)IMAGE_H && (unsigned)cidx < (unsigned)IMAGE_W) {
                unsigned char* q = s_img + (r * IMAGE_W + cidx) * 3;
                q[0] = R[i][0]; q[1] = R[i][1]; q[2] = R[i][2];
            }
        }
    }

    __syncthreads(); // image complete in smem

    // ---- Phase 3: stream out as float32 (u8 -> f32, 128-bit stores) ----
    {
        const uint32_t* s32 = reinterpret_cast<const uint32_t*>(s_img);
        float4* o4 = reinterpret_cast<float4*>(out + (size_t)m * IMG_ELEMS);
        const int n4 = IMG_ELEMS / 4; // 30000
        for (int i = threadIdx.x; i < n4; i += THREADS) {
            uint32_t w = s32[i];
            float4 f;
            f.x = (float)( w        & 0xffu);
            f.y = (float)((w >> 8)  & 0xffu);
            f.z = (float)((w >> 16) & 0xffu);
            f.w = (float)( w >> 24        );
            o4[i] = f;
        }
    }
}

extern "C" void kernel_launch(void* const* d_in, const int* in_sizes, int n_in,
                              void* d_out, int out_size) {
    const float* x          = (const float*)d_in[0]; // [B*T*6] float32
    const float* resolution = (const float*)d_in[1]; // [2]
    const float* origin     = (const float*)d_in[2]; // [2]
    float* out              = (float*)d_out;         // [B,T,200,200,3] float32

    const int M = in_sizes[0] / 6; // B*T = 800 images

    static bool attr_set = false;
    if (!attr_set) {
        cudaFuncSetAttribute(draw_rope_fused,
                             cudaFuncAttributeMaxDynamicSharedMemorySize, IMG_BYTES);
        attr_set = true;
    }

    draw_rope_fused<<<M, THREADS, IMG_BYTES>>>(x, resolution, origin, out);
}